// round 6
// baseline (speedup 1.0000x reference)
#include <cuda_runtime.h>
#include <math.h>

#define T_STEPS 20
#define NEGV -1e9f
#define FULL 0xffffffffu

__device__ __forceinline__ float fsig(float x) {
    return __fdividef(1.0f, 1.0f + __expf(-x));
}
__device__ __forceinline__ float ftanh(float x) {
    return 1.0f - __fdividef(2.0f, __expf(2.0f * x) + 1.0f);
}

__global__ __launch_bounds__(128, 1)
void controller_kernel(const float* __restrict__ w_ih,
                       const float* __restrict__ w_hh,
                       const float* __restrict__ b_ih,
                       const float* __restrict__ b_hh,
                       const float* __restrict__ g_emb,
                       const float* __restrict__ emb_kernel,
                       const float* __restrict__ emb_down,
                       const float* __restrict__ emb_up,
                       const float* __restrict__ w_kernel,
                       const float* __restrict__ w_down,
                       const float* __restrict__ w_up,
                       const float* __restrict__ noise,
                       float* __restrict__ out,
                       int out_size) {
    // Wx[e][r] = (w_ih @ emb_e)[r] + b_ih[r] + b_hh[r]
    // e: 0 = g_emb, 1..8 = emb_kernel, 9..11 = emb_down, 12..14 = emb_up
    __shared__ float Wx[15][128];
    __shared__ __align__(16) float embsh[15][32];
    __shared__ __align__(16) float hsh[4][32];        // per-warp private h
    __shared__ float act[2][128];                     // double-buffered gates
    __shared__ float gsh[160];                        // precomputed gumbels
    __shared__ __align__(16) float projsh[3][8 * 36];
    __shared__ float logsh[T_STEPS][8];               // per-step logits
    __shared__ int   ssh[T_STEPS];                    // per-step samples

    const int tid = threadIdx.x;
    const int wid = tid >> 5;
    const int j   = tid & 31;
    const int a   = j & 7;
    const int seg = j >> 3;

    // ---- load W rows for gate-row `tid` ----
    float wr[32];   // w_hh row (kept for the loop)
    float wi[32];   // w_ih row (init only)
    {
        const float4* wi4 = (const float4*)w_ih;
        const float4* wh4 = (const float4*)w_hh;
#pragma unroll
        for (int i = 0; i < 8; ++i) {
            float4 b = wh4[tid * 8 + i];
            wr[4 * i + 0] = b.x; wr[4 * i + 1] = b.y;
            wr[4 * i + 2] = b.z; wr[4 * i + 3] = b.w;
            float4 q = wi4[tid * 8 + i];
            wi[4 * i + 0] = q.x; wi[4 * i + 1] = q.y;
            wi[4 * i + 2] = q.z; wi[4 * i + 3] = q.w;
        }
    }
    const float bias = b_ih[tid] + b_hh[tid];

    // ---- stage embeddings / proj tables / gumbels ----
    for (int i = tid; i < 3 * 8 * 36; i += 128)
        ((float*)projsh)[i] = 0.0f;
    if (tid < 32) embsh[0][tid] = g_emb[tid];
    for (int i = tid; i < 8 * 32; i += 128)
        embsh[1 + (i >> 5)][i & 31] = emb_kernel[i];
    for (int i = tid; i < 3 * 32; i += 128) {
        embsh[9  + (i >> 5)][i & 31] = emb_down[i];
        embsh[12 + (i >> 5)][i & 31] = emb_up[i];
    }
    for (int i = tid; i < T_STEPS * 8; i += 128) {
        float u = noise[i];
        gsh[i] = -logf(-logf(u * (1.0f - 1e-6f) + 1e-7f));
    }
    ((float*)hsh)[tid] = 0.0f;   // h0 = 0 (all 4 warp copies)
    __syncthreads();

    for (int i = tid; i < 8 * 32; i += 128)
        projsh[0][(i >> 5) * 36 + (i & 31)] = w_kernel[i];
    for (int i = tid; i < 3 * 32; i += 128) {
        projsh[1][(i >> 5) * 36 + (i & 31)] = w_down[i];
        projsh[2][(i >> 5) * 36 + (i & 31)] = w_up[i];
    }

    // ---- precompute Wx: thread tid = row tid, all 15 entries ----
#pragma unroll 1
    for (int e = 0; e < 15; ++e) {
        const float4* em4 = (const float4*)embsh[e];
        float a0 = bias, a1 = 0.0f, a2 = 0.0f, a3 = 0.0f;
#pragma unroll
        for (int i = 0; i < 8; ++i) {
            float4 v = em4[i];
            a0 = fmaf(wi[4 * i + 0], v.x, a0);
            a1 = fmaf(wi[4 * i + 1], v.y, a1);
            a2 = fmaf(wi[4 * i + 2], v.z, a2);
            a3 = fmaf(wi[4 * i + 3], v.w, a3);
        }
        Wx[e][tid] = (a0 + a1) + (a2 + a3);
    }
    __syncthreads();

    float wxv = Wx[0][tid];          // input contribution for step 0
    float c   = 0.0f;                // per-warp lane-j cell state (replicated)
    const bool is_sig = (tid < 64) || (tid >= 96);   // warp-uniform

    int ebase = 1, nvalid = 8;
    float4 p0, p1;                   // proj registers for lane's (a, seg)

    for (int t = 0; t < T_STEPS; ++t) {
        if (t == 0 || t == 14 || t == 17) {
            const int phi = (t == 0) ? 0 : ((t == 14) ? 1 : 2);
            ebase  = (t == 0) ? 1 : ((t == 14) ? 9 : 12);
            nvalid = (t == 0) ? 8 : 3;
            const float* pr = &projsh[phi][a * 36 + seg * 8];
            p0 = *(const float4*)(pr);
            p1 = *(const float4*)(pr + 4);
        }
        const float gl = gsh[t * 8 + a];

        // ---- matvec: gate row tid = wxv + w_hh[tid] @ h ----
        float a0 = wxv, a1 = 0.0f, a2 = 0.0f, a3 = 0.0f;
        const float4* h4 = (const float4*)hsh[wid];
#pragma unroll
        for (int i = 0; i < 8; ++i) {
            float4 v = h4[i];
            a0 = fmaf(wr[4 * i + 0], v.x, a0);
            a1 = fmaf(wr[4 * i + 1], v.y, a1);
            a2 = fmaf(wr[4 * i + 2], v.z, a2);
            a3 = fmaf(wr[4 * i + 3], v.w, a3);
        }
        const float gacc = (a0 + a1) + (a2 + a3);
        const int tb = t & 1;
        act[tb][tid] = is_sig ? fsig(gacc) : ftanh(gacc);

        __syncthreads();   // the ONLY cross-warp sync per step

        // ---- redundant tail (identical in every warp -> balanced) ----
        const float ai = act[tb][j];
        const float af = act[tb][j + 32];
        const float ag = act[tb][j + 64];
        const float ao = act[tb][j + 96];
        c = fmaf(af, c, ai * ag);
        const float h = ao * ftanh(c);
        hsh[wid][j] = h;
        __syncwarp();

        const float4 h0 = ((const float4*)hsh[wid])[seg * 2];
        const float4 h1 = ((const float4*)hsh[wid])[seg * 2 + 1];
        float part = p0.x * h0.x + p0.y * h0.y + p0.z * h0.z + p0.w * h0.w
                   + p1.x * h1.x + p1.y * h1.y + p1.z * h1.z + p1.w * h1.w;
        part += __shfl_xor_sync(FULL, part, 8);
        part += __shfl_xor_sync(FULL, part, 16);
        const float logit = (a < nvalid) ? part : NEGV;

        // Gumbel-argmax over 8 classes (each aligned 8-lane group complete)
        const float v = logit + gl;
        float vm = v;
        vm = fmaxf(vm, __shfl_xor_sync(FULL, vm, 1));
        vm = fmaxf(vm, __shfl_xor_sync(FULL, vm, 2));
        vm = fmaxf(vm, __shfl_xor_sync(FULL, vm, 4));
        const unsigned bal = __ballot_sync(FULL, v == vm);
        const int s = (__ffs(bal) - 1) & 7;   // lowest class on tie

        // next step's input contribution: one LDS
        wxv = Wx[ebase + s][tid];

        // stash logits + sample for deferred stats (warp 0 only, off-path)
        if (tid < 8) {
            logsh[t][a] = logit;
            if (tid == 0) ssh[t] = s;
        }
    }

    // ---- deferred stats: 20 softmaxes in parallel (warp 0) ----
    if (wid == 0) {
        __syncwarp();
        float lp = 0.0f, ent = 0.0f;
        if (j < T_STEPS) {
            const int s = ssh[j];
            float se = 0.0f, ss1 = 0.0f;
#pragma unroll
            for (int k = 0; k < 8; ++k) {
                const float l = logsh[j][k];
                const float e = __expf(l);    // masked -> exact +0
                se  += e;
                ss1 += e * l;
            }
            const float lse = __logf(se);
            lp  = logsh[j][s] - lse;
            ent = lse - __fdividef(ss1, se);
            out[2 + j] = (float)s;
        }
#pragma unroll
        for (int o = 16; o > 0; o >>= 1) {
            lp  += __shfl_xor_sync(FULL, lp,  o);
            ent += __shfl_xor_sync(FULL, ent, o);
        }
        if (j == 0) {
            out[0] = lp;
            out[1] = ent;
        }
    }
}

extern "C" void kernel_launch(void* const* d_in, const int* in_sizes, int n_in,
                              void* d_out, int out_size) {
    const float* w_ih       = (const float*)d_in[0];
    const float* w_hh       = (const float*)d_in[1];
    const float* b_ih       = (const float*)d_in[2];
    const float* b_hh       = (const float*)d_in[3];
    const float* g_emb      = (const float*)d_in[4];
    const float* emb_kernel = (const float*)d_in[5];
    const float* emb_down   = (const float*)d_in[6];
    const float* emb_up     = (const float*)d_in[7];
    const float* w_kernel   = (const float*)d_in[8];
    const float* w_down     = (const float*)d_in[9];
    const float* w_up       = (const float*)d_in[10];
    const float* noise      = (const float*)d_in[11];
    float* out = (float*)d_out;

    controller_kernel<<<1, 128>>>(w_ih, w_hh, b_ih, b_hh, g_emb,
                                  emb_kernel, emb_down, emb_up,
                                  w_kernel, w_down, w_up, noise,
                                  out, out_size);
}

// round 7
// speedup vs baseline: 1.1530x; 1.1530x over previous
#include <cuda_runtime.h>
#include <math.h>

#define T_STEPS 20
#define NEGV -1e9f
#define FULL 0xffffffffu

__device__ __forceinline__ float tanhapx(float x) {
    float y;
    asm("tanh.approx.f32 %0, %1;" : "=f"(y) : "f"(x));
    return y;
}
__device__ __forceinline__ float sigapx(float x) {
    return fmaf(0.5f, tanhapx(0.5f * x), 0.5f);
}
// monotone float->uint key (total order, incl. negatives)
__device__ __forceinline__ unsigned sortable(float v) {
    unsigned b = __float_as_uint(v);
    return b ^ (unsigned)(((int)b >> 31) | 0x80000000);
}

__global__ __launch_bounds__(128, 1)
void controller_kernel(const float* __restrict__ w_ih,
                       const float* __restrict__ w_hh,
                       const float* __restrict__ b_ih,
                       const float* __restrict__ b_hh,
                       const float* __restrict__ g_emb,
                       const float* __restrict__ emb_kernel,
                       const float* __restrict__ emb_down,
                       const float* __restrict__ emb_up,
                       const float* __restrict__ w_kernel,
                       const float* __restrict__ w_down,
                       const float* __restrict__ w_up,
                       const float* __restrict__ noise,
                       float* __restrict__ out,
                       int out_size) {
    // Wx[e][r] = (w_ih @ emb_e)[r] + b_ih[r] + b_hh[r]
    // e: 0 = g_emb, 1..8 = kernel, 9..11 = down, 12..14 = up
    __shared__ float Wx[15][128];
    __shared__ __align__(16) float embsh[15][32];
    __shared__ __align__(16) float hsh[4][32];   // per-warp private h
    __shared__ float act[2][128];                // double-buffered activations
    __shared__ float gsh[160];                   // precomputed gumbels
    __shared__ __align__(16) float projsh[3][8 * 36];
    __shared__ float logsh[T_STEPS][8];
    __shared__ int   ssh[T_STEPS];

    const int tid = threadIdx.x;
    const int wid = tid >> 5;
    const int j   = tid & 31;
    const int a   = j & 7;
    const int seg = j >> 3;
    const int sb  = seg * 8;

    // ---- load W rows for gate-row `tid` ----
    float wr[32];   // w_hh row (loop)
    float wi[32];   // w_ih row (init only)
    {
        const float4* wi4 = (const float4*)w_ih;
        const float4* wh4 = (const float4*)w_hh;
#pragma unroll
        for (int i = 0; i < 8; ++i) {
            float4 b = wh4[tid * 8 + i];
            wr[4 * i + 0] = b.x; wr[4 * i + 1] = b.y;
            wr[4 * i + 2] = b.z; wr[4 * i + 3] = b.w;
            float4 q = wi4[tid * 8 + i];
            wi[4 * i + 0] = q.x; wi[4 * i + 1] = q.y;
            wi[4 * i + 2] = q.z; wi[4 * i + 3] = q.w;
        }
    }
    const float bias = b_ih[tid] + b_hh[tid];

    // ---- stage embeddings / proj tables / gumbels ----
    for (int i = tid; i < 3 * 8 * 36; i += 128)
        ((float*)projsh)[i] = 0.0f;
    if (tid < 32) embsh[0][tid] = g_emb[tid];
    for (int i = tid; i < 8 * 32; i += 128)
        embsh[1 + (i >> 5)][i & 31] = emb_kernel[i];
    for (int i = tid; i < 3 * 32; i += 128) {
        embsh[9  + (i >> 5)][i & 31] = emb_down[i];
        embsh[12 + (i >> 5)][i & 31] = emb_up[i];
    }
    for (int i = tid; i < T_STEPS * 8; i += 128) {
        float u = noise[i];
        gsh[i] = -logf(-logf(u * (1.0f - 1e-6f) + 1e-7f));
    }
    ((float*)hsh)[tid] = 0.0f;
    __syncthreads();

    for (int i = tid; i < 8 * 32; i += 128)
        projsh[0][(i >> 5) * 36 + (i & 31)] = w_kernel[i];
    for (int i = tid; i < 3 * 32; i += 128) {
        projsh[1][(i >> 5) * 36 + (i & 31)] = w_down[i];
        projsh[2][(i >> 5) * 36 + (i & 31)] = w_up[i];
    }

    // ---- precompute Wx ----
#pragma unroll 1
    for (int e = 0; e < 15; ++e) {
        const float4* em4 = (const float4*)embsh[e];
        float a0 = bias, a1 = 0.0f, a2 = 0.0f, a3 = 0.0f;
#pragma unroll
        for (int i = 0; i < 8; ++i) {
            float4 v = em4[i];
            a0 = fmaf(wi[4 * i + 0], v.x, a0);
            a1 = fmaf(wi[4 * i + 1], v.y, a1);
            a2 = fmaf(wi[4 * i + 2], v.z, a2);
            a3 = fmaf(wi[4 * i + 3], v.w, a3);
        }
        Wx[e][tid] = (a0 + a1) + (a2 + a3);
    }
    __syncthreads();

    const bool is_sig = (tid < 64) || (tid >= 96);   // warp-uniform

    // phase-0 state: proj regs, candidate Wx prefetch, nvalid
    int nvalid = 8;
    float4 p0v, p1v;
    {
        const float* pr = &projsh[0][a * 36 + sb];
        p0v = *(const float4*)(pr);
        p1v = *(const float4*)(pr + 4);
    }
    float w0 = Wx[1][tid], w1 = Wx[2][tid], w2 = Wx[3][tid], w3 = Wx[4][tid];
    float w4 = Wx[5][tid], w5 = Wx[6][tid], w6 = Wx[7][tid], w7 = Wx[8][tid];

    // act for t=0: h0 = 0 -> gacc = Wx[0]
    {
        const float g0 = Wx[0][tid];
        act[0][tid] = is_sig ? sigapx(g0) : tanhapx(g0);
    }
    float c = 0.0f;
    __syncthreads();

    for (int t = 0; t < T_STEPS; ++t) {
        // phase change (affects logits of this step AND emb candidates)
        if (t == 14 || t == 17) {
            const int phi = (t == 14) ? 1 : 2;
            const int eb  = (t == 14) ? 9 : 12;
            nvalid = 3;
            const float* pr = &projsh[phi][a * 36 + sb];
            p0v = *(const float4*)(pr);
            p1v = *(const float4*)(pr + 4);
            w0 = Wx[eb][tid]; w1 = Wx[eb + 1][tid]; w2 = Wx[eb + 2][tid];
            // w3..w7 stale but unreachable (s < 3)
        }
        const int tb = t & 1;
        const float gl = gsh[t * 8 + a];

        // ---- LSTM cell from activations ----
        const float ai = act[tb][j];
        const float af = act[tb][j + 32];
        const float ag = act[tb][j + 64];
        const float ao = act[tb][j + 96];
        c = fmaf(af, c, ai * ag);
        const float h = ao * tanhapx(c);

        // ---- logits: gather 8 h values via shfl, dot with proj regs ----
        float l0 = p0v.x * __shfl_sync(FULL, h, sb + 0);
        float l1 = p0v.y * __shfl_sync(FULL, h, sb + 1);
        l0 = fmaf(p0v.z, __shfl_sync(FULL, h, sb + 2), l0);
        l1 = fmaf(p0v.w, __shfl_sync(FULL, h, sb + 3), l1);
        l0 = fmaf(p1v.x, __shfl_sync(FULL, h, sb + 4), l0);
        l1 = fmaf(p1v.y, __shfl_sync(FULL, h, sb + 5), l1);
        l0 = fmaf(p1v.z, __shfl_sync(FULL, h, sb + 6), l0);
        l1 = fmaf(p1v.w, __shfl_sync(FULL, h, sb + 7), l1);
        float part = l0 + l1;
        part += __shfl_xor_sync(FULL, part, 8);
        part += __shfl_xor_sync(FULL, part, 16);
        const float logit = (a < nvalid) ? part : NEGV;

        // ---- publish h; start next-step w_hh @ h matvec (ILP w/ argmax) ----
        hsh[wid][j] = h;
        __syncwarp();
        float a0 = 0.0f, a1 = 0.0f, a2 = 0.0f, a3 = 0.0f;
        const float4* h4 = (const float4*)hsh[wid];
#pragma unroll
        for (int i = 0; i < 8; ++i) {
            float4 v = h4[i];
            a0 = fmaf(wr[4 * i + 0], v.x, a0);
            a1 = fmaf(wr[4 * i + 1], v.y, a1);
            a2 = fmaf(wr[4 * i + 2], v.z, a2);
            a3 = fmaf(wr[4 * i + 3], v.w, a3);
        }
        const float ghh = (a0 + a1) + (a2 + a3);

        // ---- Gumbel-argmax: u32 redux on sortable key ----
        const unsigned key = sortable(logit + gl);
        unsigned km;
        asm("redux.sync.max.u32 %0, %1, 0xffffffff;" : "=r"(km) : "r"(key));
        const unsigned bal = __ballot_sync(FULL, key == km);
        const int s = (__ffs(bal) - 1) & 7;     // lowest class on tie

        // stash for deferred stats (warp 0)
        if (tid < 8) {
            logsh[t][a] = logit;
            if (tid == 0) ssh[t] = s;
        }

        // ---- select sampled Wx candidate (3-level SEL tree) ----
        if (t < T_STEPS - 1) {
            const float t01 = (s & 1) ? w1 : w0;
            const float t23 = (s & 1) ? w3 : w2;
            const float t45 = (s & 1) ? w5 : w4;
            const float t67 = (s & 1) ? w7 : w6;
            const float t03 = (s & 2) ? t23 : t01;
            const float t47 = (s & 2) ? t67 : t45;
            const float wx  = (s & 4) ? t47 : t03;
            const float gacc = ghh + wx;
            act[tb ^ 1][tid] = is_sig ? sigapx(gacc) : tanhapx(gacc);
        }
        __syncthreads();
    }

    // ---- deferred stats: 20 softmaxes in parallel (warp 0) ----
    if (wid == 0) {
        __syncwarp();
        float lp = 0.0f, ent = 0.0f;
        if (j < T_STEPS) {
            const int s = ssh[j];
            float se = 0.0f, ss1 = 0.0f;
#pragma unroll
            for (int k = 0; k < 8; ++k) {
                const float l = logsh[j][k];
                const float e = __expf(l);    // masked -> exact +0
                se  += e;
                ss1 += e * l;
            }
            const float lse = __logf(se);
            lp  = logsh[j][s] - lse;
            ent = lse - __fdividef(ss1, se);
            out[2 + j] = (float)s;
        }
#pragma unroll
        for (int o = 16; o > 0; o >>= 1) {
            lp  += __shfl_xor_sync(FULL, lp,  o);
            ent += __shfl_xor_sync(FULL, ent, o);
        }
        if (j == 0) {
            out[0] = lp;
            out[1] = ent;
        }
    }
}

extern "C" void kernel_launch(void* const* d_in, const int* in_sizes, int n_in,
                              void* d_out, int out_size) {
    const float* w_ih       = (const float*)d_in[0];
    const float* w_hh       = (const float*)d_in[1];
    const float* b_ih       = (const float*)d_in[2];
    const float* b_hh       = (const float*)d_in[3];
    const float* g_emb      = (const float*)d_in[4];
    const float* emb_kernel = (const float*)d_in[5];
    const float* emb_down   = (const float*)d_in[6];
    const float* emb_up     = (const float*)d_in[7];
    const float* w_kernel   = (const float*)d_in[8];
    const float* w_down     = (const float*)d_in[9];
    const float* w_up       = (const float*)d_in[10];
    const float* noise      = (const float*)d_in[11];
    float* out = (float*)d_out;

    controller_kernel<<<1, 128>>>(w_ih, w_hh, b_ih, b_hh, g_emb,
                                  emb_kernel, emb_down, emb_up,
                                  w_kernel, w_down, w_up, noise,
                                  out, out_size);
}